// round 1
// baseline (speedup 1.0000x reference)
#include <cuda_runtime.h>
#include <math.h>

#define NB 32
#define NS 2048
#define NH 768
#define NO 768
#define NK 64

// scratch for pooled (b, h) between kernels (no cudaMalloc allowed)
__device__ float g_pooled[NB * NH];

// ---------------------------------------------------------------------------
// Kernel A: per-batch sparse attention pooling.
// grid = NB blocks, 256 threads each.
// ---------------------------------------------------------------------------
__global__ void __launch_bounds__(256)
attn_pool_kernel(const float* __restrict__ hidden,       // (B,S,H)
                 const int*   __restrict__ token_idxs,   // (B,K) sorted
                 const float* __restrict__ subject_hidden,// (B,H)
                 const float* __restrict__ Wa,           // (2H,1)
                 const float* __restrict__ ba,           // (1,)
                 float*       __restrict__ out_aw)       // (B,S)
{
    const int b    = blockIdx.x;
    const int tid  = threadIdx.x;
    const int warp = tid >> 5;
    const int lane = tid & 31;

    __shared__ int   s_idx[NK];
    __shared__ long  s_off[NK];
    __shared__ float s_score[NK];
    __shared__ float s_w[NK];
    __shared__ float s_red[8];
    __shared__ float s_subj;

    // zero this batch's attention-weight row (S floats)
    float* aw = out_aw + (size_t)b * NS;
    #pragma unroll
    for (int i = tid; i < NS; i += 256) aw[i] = 0.0f;

    if (tid < NK) {
        int ix = token_idxs[b * NK + tid];
        s_idx[tid] = ix;
        s_off[tid] = (long)ix * NH;
    }
    __syncthreads();

    // ---- subject score: dot(subject_hidden[b], Wa[0:H]) + ba ----
    {
        const float* sh = subject_hidden + (size_t)b * NH;
        float p = 0.f;
        for (int i = tid; i < NH; i += 256) p = fmaf(sh[i], Wa[i], p);
        #pragma unroll
        for (int o = 16; o; o >>= 1) p += __shfl_xor_sync(0xffffffffu, p, o);
        if (lane == 0) s_red[warp] = p;
    }
    __syncthreads();
    if (tid == 0) {
        float t = 0.f;
        #pragma unroll
        for (int w = 0; w < 8; w++) t += s_red[w];
        s_subj = t + ba[0];
    }

    // ---- per-token scores: dot(hidden[b, idx_j], Wa[H:2H]) ----
    const float* hb  = hidden + (size_t)b * NS * NH;
    const float* Wa2 = Wa + NH;
    #pragma unroll
    for (int j = warp; j < NK; j += 8) {
        const float* row = hb + s_off[j];
        float p = 0.f;
        #pragma unroll 8
        for (int i = lane; i < NH; i += 32) p = fmaf(row[i], Wa2[i], p);
        #pragma unroll
        for (int o = 16; o; o >>= 1) p += __shfl_xor_sync(0xffffffffu, p, o);
        if (lane == 0) s_score[j] = p;
    }
    __syncthreads();

    // ---- dedup'd softmax over the K entries (warp 0; 2 entries/lane) ----
    if (warp == 0) {
        float sc[2];
        bool  v[2];
        float m = -1e30f;
        #pragma unroll
        for (int r = 0; r < 2; r++) {
            int j = lane + 32 * r;
            v[r]  = (j == 0) || (s_idx[j] != s_idx[j - 1]);  // sorted -> adjacency dedup
            sc[r] = s_score[j] + s_subj;
            m = fmaxf(m, v[r] ? sc[r] : -1e30f);
        }
        #pragma unroll
        for (int o = 16; o; o >>= 1) m = fmaxf(m, __shfl_xor_sync(0xffffffffu, m, o));
        float e[2], sum = 0.f;
        #pragma unroll
        for (int r = 0; r < 2; r++) {
            e[r] = v[r] ? expf(sc[r] - m) : 0.f;
            sum += e[r];
        }
        #pragma unroll
        for (int o = 16; o; o >>= 1) sum += __shfl_xor_sync(0xffffffffu, sum, o);
        float inv = 1.0f / sum;
        #pragma unroll
        for (int r = 0; r < 2; r++) s_w[lane + 32 * r] = e[r] * inv;
    }
    __syncthreads();

    // ---- scatter attention weights at valid positions ----
    if (tid < NK) {
        bool valid = (tid == 0) || (s_idx[tid] != s_idx[tid - 1]);
        if (valid) aw[s_idx[tid]] = s_w[tid];
    }

    // ---- pooled[b,h] = sum_j w_j * hidden[b, idx_j, h]  (w_j = 0 for dups) ----
    for (int h = tid; h < NH; h += 256) {
        float acc = 0.f;
        #pragma unroll 8
        for (int j = 0; j < NK; j++)
            acc = fmaf(s_w[j], hb[s_off[j] + h], acc);
        g_pooled[b * NH + h] = acc;
    }
}

// ---------------------------------------------------------------------------
// Kernel B: transformed = tanh(pooled @ Wo + bo)
// grid = (NO/128 o-tiles, NB/4 batch groups), 128 threads.
// Each thread: one output column for 4 batches.
// ---------------------------------------------------------------------------
__global__ void __launch_bounds__(128)
out_gemm_kernel(const float* __restrict__ Wo,   // (H,O) row-major
                const float* __restrict__ bo,   // (O,)
                float*       __restrict__ out_t)// (B,O)
{
    const int tile = blockIdx.x;       // 0..5
    const int bg   = blockIdx.y;       // 0..7
    const int tid  = threadIdx.x;      // 0..127
    const int o    = tile * 128 + tid;
    const int b0   = bg * 4;

    __shared__ float s_p[4 * NH];      // pooled rows for 4 batches (12 KB)
    #pragma unroll
    for (int i = tid; i < 4 * NH; i += 128)
        s_p[i] = g_pooled[b0 * NH + i];
    __syncthreads();

    float a0 = 0.f, a1 = 0.f, a2 = 0.f, a3 = 0.f;
    const float* w = Wo + o;
    #pragma unroll 4
    for (int h = 0; h < NH; h++) {
        float wv = w[(size_t)h * NO];
        a0 = fmaf(s_p[h],            wv, a0);
        a1 = fmaf(s_p[NH + h],       wv, a1);
        a2 = fmaf(s_p[2 * NH + h],   wv, a2);
        a3 = fmaf(s_p[3 * NH + h],   wv, a3);
    }
    const float bv = bo[o];
    out_t[(size_t)(b0 + 0) * NO + o] = tanhf(a0 + bv);
    out_t[(size_t)(b0 + 1) * NO + o] = tanhf(a1 + bv);
    out_t[(size_t)(b0 + 2) * NO + o] = tanhf(a2 + bv);
    out_t[(size_t)(b0 + 3) * NO + o] = tanhf(a3 + bv);
}

// ---------------------------------------------------------------------------
extern "C" void kernel_launch(void* const* d_in, const int* in_sizes, int n_in,
                              void* d_out, int out_size)
{
    const float* hidden         = (const float*)d_in[0];
    const int*   token_idxs     = (const int*)  d_in[1];
    const float* subject_hidden = (const float*)d_in[2];
    const float* Wa             = (const float*)d_in[3];
    const float* ba             = (const float*)d_in[4];
    const float* Wo             = (const float*)d_in[5];
    const float* bo             = (const float*)d_in[6];

    float* out_transformed = (float*)d_out;              // (B,O) = 24576 floats
    float* out_aw          = (float*)d_out + NB * NO;    // (B,S) = 65536 floats

    attn_pool_kernel<<<NB, 256>>>(hidden, token_idxs, subject_hidden,
                                  Wa, ba, out_aw);
    out_gemm_kernel<<<dim3(NO / 128, NB / 4), 128>>>(Wo, bo, out_transformed);
}

// round 2
// speedup vs baseline: 3.6336x; 3.6336x over previous
#include <cuda_runtime.h>
#include <math.h>

#define NB 32
#define NS 2048
#define NH 768
#define NO 768
#define NK 64
#define HSPLIT 24
#define HCHUNK (NH / HSPLIT)   // 32

// inter-kernel scratch (no cudaMalloc allowed)
__device__ float g_score[NB * 72];          // [b][0..63]=token scores, [b][64]=subject dot + ba
__device__ float g_pooled[NB * NH];         // [b][h]
__device__ float g_part[HSPLIT * NB * NO];  // [hs][b][o] partial GEMM sums

// ---------------------------------------------------------------------------
// K1: per-(batch, token) score dots + per-batch subject dot.
// grid = (NB, 9), 256 threads (8 warps).
//   y < 8 : warp w computes dot(hidden[b, idx[y*8+w]], Wa[H:2H])
//   y == 8: whole block computes dot(subject_hidden[b], Wa[0:H]) + ba
// ---------------------------------------------------------------------------
__global__ void __launch_bounds__(256)
score_kernel(const float* __restrict__ hidden,
             const int*   __restrict__ token_idxs,
             const float* __restrict__ subject_hidden,
             const float* __restrict__ Wa,
             const float* __restrict__ ba)
{
    const int b    = blockIdx.x;
    const int y    = blockIdx.y;
    const int tid  = threadIdx.x;
    const int warp = tid >> 5;
    const int lane = tid & 31;

    if (y < 8) {
        const int j  = y * 8 + warp;
        const int ix = token_idxs[b * NK + j];
        const float4* row = (const float4*)(hidden + ((size_t)b * NS + ix) * NH);
        const float4* w4  = (const float4*)(Wa + NH);
        float p = 0.f;
        #pragma unroll
        for (int i = 0; i < 6; i++) {           // 6*32*4 = 768
            float4 r = row[i * 32 + lane];
            float4 w = w4[i * 32 + lane];
            p = fmaf(r.x, w.x, p);
            p = fmaf(r.y, w.y, p);
            p = fmaf(r.z, w.z, p);
            p = fmaf(r.w, w.w, p);
        }
        #pragma unroll
        for (int o = 16; o; o >>= 1) p += __shfl_xor_sync(0xffffffffu, p, o);
        if (lane == 0) g_score[b * 72 + j] = p;
    } else {
        __shared__ float s_red[8];
        const float4* sh = (const float4*)(subject_hidden + (size_t)b * NH);
        const float4* w4 = (const float4*)Wa;
        float p = 0.f;
        // 192 float4 over 256 threads: thread tid handles tid if tid<192
        if (tid < 192) {
            float4 r = sh[tid];
            float4 w = w4[tid];
            p = r.x * w.x + r.y * w.y + r.z * w.z + r.w * w.w;
        }
        #pragma unroll
        for (int o = 16; o; o >>= 1) p += __shfl_xor_sync(0xffffffffu, p, o);
        if (lane == 0) s_red[warp] = p;
        __syncthreads();
        if (tid == 0) {
            float t = 0.f;
            #pragma unroll
            for (int w = 0; w < 8; w++) t += s_red[w];
            g_score[b * 72 + 64] = t + ba[0];
        }
    }
}

// ---------------------------------------------------------------------------
// K2: dedup softmax (recomputed per block, trivial) + weighted gather pool.
// grid = (NB, 6 h-tiles), 128 threads. Tile-0 blocks also zero+scatter aw.
// ---------------------------------------------------------------------------
__global__ void __launch_bounds__(128)
pool_kernel(const float* __restrict__ hidden,
            const int*   __restrict__ token_idxs,
            float*       __restrict__ out_aw)   // (B,S)
{
    const int b    = blockIdx.x;
    const int yt   = blockIdx.y;
    const int tid  = threadIdx.x;
    const int lane = tid & 31;

    __shared__ int    s_idx[NK];
    __shared__ size_t s_off[NK];
    __shared__ float  s_sc[NK];
    __shared__ float  s_w[NK];

    if (tid < NK) {
        int ix = token_idxs[b * NK + tid];
        s_idx[tid] = ix;
        s_off[tid] = (size_t)ix * NH;
        s_sc[tid]  = g_score[b * 72 + tid];
    }
    __syncthreads();

    const float subj = g_score[b * 72 + 64];

    // warp 0: dedup'd softmax over the 64 entries (2/lane)
    if (tid < 32) {
        float sc[2]; bool v[2];
        float m = -1e30f;
        #pragma unroll
        for (int r = 0; r < 2; r++) {
            int j = lane + 32 * r;
            v[r]  = (j == 0) || (s_idx[j] != s_idx[j - 1]);
            sc[r] = s_sc[j] + subj;
            m = fmaxf(m, v[r] ? sc[r] : -1e30f);
        }
        #pragma unroll
        for (int o = 16; o; o >>= 1) m = fmaxf(m, __shfl_xor_sync(0xffffffffu, m, o));
        float e[2], sum = 0.f;
        #pragma unroll
        for (int r = 0; r < 2; r++) { e[r] = v[r] ? expf(sc[r] - m) : 0.f; sum += e[r]; }
        #pragma unroll
        for (int o = 16; o; o >>= 1) sum += __shfl_xor_sync(0xffffffffu, sum, o);
        float inv = 1.0f / sum;
        #pragma unroll
        for (int r = 0; r < 2; r++) s_w[lane + 32 * r] = e[r] * inv;
    }
    __syncthreads();

    // tile-0 block: zero aw row, then scatter weights
    if (yt == 0) {
        float* aw = out_aw + (size_t)b * NS;
        #pragma unroll
        for (int i = tid; i < NS; i += 128) aw[i] = 0.0f;
        __syncthreads();
        if (tid < NK) {
            bool valid = (tid == 0) || (s_idx[tid] != s_idx[tid - 1]);
            if (valid) aw[s_idx[tid]] = s_w[tid];
        }
    }

    // pool this 128-wide h tile (rows are L2-hot from K1)
    const float* hb = hidden + (size_t)b * NS * NH;
    const int h = yt * 128 + tid;
    float acc = 0.f;
    #pragma unroll 8
    for (int j = 0; j < NK; j++)
        acc = fmaf(s_w[j], hb[s_off[j] + h], acc);
    g_pooled[b * NH + h] = acc;
}

// ---------------------------------------------------------------------------
// K3: GEMM partials. grid = (NO/128, HSPLIT), 128 threads.
// Each thread: one o-column, 32 batch accumulators, HCHUNK=32 h values.
// Wo is read exactly once across the whole grid.
// ---------------------------------------------------------------------------
__global__ void __launch_bounds__(128)
gemm_part_kernel(const float* __restrict__ Wo)   // (H,O) row-major
{
    const int o  = blockIdx.x * 128 + threadIdx.x;
    const int h0 = blockIdx.y * HCHUNK;
    const int tid = threadIdx.x;

    __shared__ float s_p[NB * HCHUNK];   // [b][hh], 4 KB
    #pragma unroll
    for (int i = tid; i < NB * HCHUNK; i += 128) {
        int bb = i >> 5, hh = i & (HCHUNK - 1);
        s_p[i] = g_pooled[bb * NH + h0 + hh];
    }
    __syncthreads();

    float acc[NB];
    #pragma unroll
    for (int bb = 0; bb < NB; bb++) acc[bb] = 0.f;

    const float* w = Wo + (size_t)h0 * NO + o;
    #pragma unroll 4
    for (int hh = 0; hh < HCHUNK; hh++) {
        float wv = w[(size_t)hh * NO];
        #pragma unroll
        for (int bb = 0; bb < NB; bb++)
            acc[bb] = fmaf(s_p[bb * HCHUNK + hh], wv, acc[bb]);
    }

    float* dst = g_part + (size_t)blockIdx.y * NB * NO + o;
    #pragma unroll
    for (int bb = 0; bb < NB; bb++)
        dst[(size_t)bb * NO] = acc[bb];
}

// ---------------------------------------------------------------------------
// K4: finalize — sum HSPLIT partials, add bias, tanh.
// grid = NB*NO/128 = 192 blocks, 128 threads.
// ---------------------------------------------------------------------------
__global__ void __launch_bounds__(128)
finalize_kernel(const float* __restrict__ bo,
                float*       __restrict__ out_t)  // (B,O)
{
    const int idx = blockIdx.x * 128 + threadIdx.x;   // linear over [b][o]
    const int o   = idx % NO;
    float sum = bo[o];
    #pragma unroll
    for (int hs = 0; hs < HSPLIT; hs++)
        sum += g_part[(size_t)hs * NB * NO + idx];
    out_t[idx] = tanhf(sum);
}

// ---------------------------------------------------------------------------
extern "C" void kernel_launch(void* const* d_in, const int* in_sizes, int n_in,
                              void* d_out, int out_size)
{
    const float* hidden         = (const float*)d_in[0];
    const int*   token_idxs     = (const int*)  d_in[1];
    const float* subject_hidden = (const float*)d_in[2];
    const float* Wa             = (const float*)d_in[3];
    const float* ba             = (const float*)d_in[4];
    const float* Wo             = (const float*)d_in[5];
    const float* bo             = (const float*)d_in[6];

    float* out_transformed = (float*)d_out;              // (B,O)
    float* out_aw          = (float*)d_out + NB * NO;    // (B,S)

    score_kernel<<<dim3(NB, 9), 256>>>(hidden, token_idxs, subject_hidden, Wa, ba);
    pool_kernel<<<dim3(NB, 6), 128>>>(hidden, token_idxs, out_aw);
    gemm_part_kernel<<<dim3(NO / 128, HSPLIT), 128>>>(Wo);
    finalize_kernel<<<(NB * NO) / 128, 128>>>(bo, out_transformed);
}